// round 17
// baseline (speedup 1.0000x reference)
#include <cuda_runtime.h>
#include <math_constants.h>

// D_KNN soft-kNN imputation — persistent kernel, TMA-bulk (UBLKCP) pipeline.
//   inputs: X_train [N,64] f32, y_train [N,64] f32, X_missing [64] f32
//   output: [1,64] f32
//
// 296 blocks (2/SM) x 128 threads. Each block streams contiguous 128-row
// (32KB) tiles of X via cp.async.bulk 1D into a 3-slot smem ring with
// mbarrier complete_tx (full) / arrival (empty) handshakes — requests live
// in the DMA engine, not the LSU (which capped cp.async at ~1KB/warp in
// flight). One thread = one row; bank conflicts from the unpadded bulk
// layout killed by per-thread column rotation (tid+k)&15 with q duplicated.
// Selection: threshold + per-warp smem candidate buffer, bitonic flush.
// Two-tier last-block election merges 296 sorted lists (296 = 8*37).

#define NBLK 296
#define T1   128
#define NWRP 4
#define GSZ  37
#define NGRP 8
#define KSEL 32
#define DIMS 64
#define ROWS 128                  // rows per tile (contiguous 32KB)
#define TILE_F4 (ROWS * 16)       // 2048 float4
#define NSTG 3

typedef unsigned long long u64;
typedef unsigned int u32;

__device__ u64   g_btop[NBLK * KSEL];
__device__ float g_bz[NBLK];
__device__ u64   g_gtop[NGRP * KSEL];
__device__ float g_gz[NGRP];
__device__ int   g_c1[NGRP];      // tier-1 counters (zero-init, self-reset)
__device__ int   g_c2 = 0;        // tier-2 counter

// ---- warp-collective helpers ----

__device__ __forceinline__ u64 bsort32(u64 key, int lane) {
    #pragma unroll
    for (int k = 2; k <= 32; k <<= 1) {
        #pragma unroll
        for (int j = k >> 1; j; j >>= 1) {
            u64 p = __shfl_xor_sync(0xffffffffu, key, j);
            bool keepMin = (((lane & j) == 0) == ((lane & k) == 0));
            key = keepMin ? (key < p ? key : p) : (key > p ? key : p);
        }
    }
    return key;
}

__device__ __forceinline__ u64 bmerge32(u64 key, int lane) {
    #pragma unroll
    for (int j = 16; j; j >>= 1) {
        u64 p = __shfl_xor_sync(0xffffffffu, key, j);
        key = ((lane & j) == 0) ? (key < p ? key : p) : (key > p ? key : p);
    }
    return key;
}

__device__ __forceinline__ u64 merge_sorted(u64 a, u64 b, int lane) {
    u64 br = __shfl_sync(0xffffffffu, b, 31 - lane);
    a = (a < br) ? a : br;
    return bmerge32(a, lane);
}

__device__ __forceinline__ void flush_cands(volatile u64* wbuf, volatile int* wcnt,
                                            u64& held, u32& mhi, int lane) {
    __syncwarp();
    const int n = *wcnt;
    u64 c = (lane < n) ? wbuf[lane] : ~0ull;
    c = bsort32(c, lane);
    held = merge_sorted(held, c, lane);
    if (n > 32) {
        u64 c2 = (32 + lane < n) ? wbuf[32 + lane] : ~0ull;
        c2 = bsort32(c2, lane);
        held = merge_sorted(held, c2, lane);
    }
    __syncwarp();
    if (lane == 0) *wcnt = 0;
    __syncwarp();
    mhi = (u32)(__shfl_sync(0xffffffffu, held, 31) >> 32);
}

// ---- mbarrier / TMA-bulk primitives ----

__device__ __forceinline__ u32 smem_u32(const void* p) {
    return (u32)__cvta_generic_to_shared(p);
}

__device__ __forceinline__ void mbar_init(u32 a, u32 cnt) {
    asm volatile("mbarrier.init.shared.b64 [%0], %1;" :: "r"(a), "r"(cnt) : "memory");
}
__device__ __forceinline__ void mbar_expect_tx(u32 a, u32 bytes) {
    asm volatile("mbarrier.arrive.expect_tx.shared.b64 _, [%0], %1;"
                 :: "r"(a), "r"(bytes) : "memory");
}
__device__ __forceinline__ void mbar_arrive(u32 a) {
    asm volatile("mbarrier.arrive.shared.b64 _, [%0];" :: "r"(a) : "memory");
}
__device__ __forceinline__ void mbar_wait(u32 a, u32 ph) {
    u32 done;
    do {
        asm volatile(
            "{\n\t.reg .pred p;\n\t"
            "mbarrier.try_wait.parity.acquire.cta.shared::cta.b64 p, [%1], %2, 0x989680;\n\t"
            "selp.b32 %0, 1, 0, p;\n\t}"
            : "=r"(done) : "r"(a), "r"(ph) : "memory");
    } while (!done);
}
__device__ __forceinline__ void tma_bulk_1d(u32 dst, const void* src, u32 bytes,
                                            u32 mbar) {
    asm volatile(
        "cp.async.bulk.shared::cluster.global.mbarrier::complete_tx::bytes "
        "[%0], [%1], %2, [%3];"
        :: "r"(dst), "l"(src), "r"(bytes), "r"(mbar) : "memory");
}

__global__ void __launch_bounds__(T1)
knn_fused(const float* __restrict__ X, const float* __restrict__ Y,
          const float* __restrict__ q, float* __restrict__ out, int N) {
    extern __shared__ float4 smem[];      // [NSTG*TILE_F4] tiles + qsd[32]
    float4* qsd = smem + NSTG * TILE_F4;  // q duplicated x2 (mask-free index)

    __shared__ u64 s_lists[NWRP][KSEL];
    __shared__ u64 wbuf[NWRP][64];
    __shared__ int wcnt[NWRP];
    __shared__ float s_z[NWRP];
    __shared__ float wv[KSEL];
    __shared__ int   iv[KSEL];
    __shared__ float zinv_s;
    __shared__ int amLast1, amLast2;
    __shared__ u64 mbar_full[NSTG], mbar_empty[NSTG];

    const int tid  = threadIdx.x;
    const int lane = tid & 31;
    const int warp = tid >> 5;
    const int tiles = (N + ROWS - 1) / ROWS;

    if (tid < 16) {
        const float4 v = __ldg((const float4*)q + tid);
        qsd[tid] = v;
        qsd[tid + 16] = v;
    }
    if (tid < NWRP) wcnt[tid] = 0;
    if (tid == 0) {
        #pragma unroll
        for (int s = 0; s < NSTG; s++) {
            mbar_init(smem_u32(&mbar_full[s]), 1);
            mbar_init(smem_u32(&mbar_empty[s]), T1);
        }
    }
    __syncthreads();

    u32 fullA[NSTG], emptyA[NSTG];
    #pragma unroll
    for (int s = 0; s < NSTG; s++) {
        fullA[s]  = smem_u32(&mbar_full[s]);
        emptyA[s] = smem_u32(&mbar_empty[s]);
    }
    const u32 dstBase = smem_u32(smem);
    const int t0 = blockIdx.x;

    // producer prologue (thread 0): fill slots 0,1
    if (tid == 0) {
        {
            const int rows = min(ROWS, N - t0 * ROWS);
            const u32 bytes = (u32)rows * DIMS * 4u;
            mbar_expect_tx(fullA[0], bytes);
            tma_bulk_1d(dstBase, X + (size_t)t0 * ROWS * DIMS, bytes, fullA[0]);
        }
        if (t0 + NBLK < tiles) {
            const int t1 = t0 + NBLK;
            const int rows = min(ROWS, N - t1 * ROWS);
            const u32 bytes = (u32)rows * DIMS * 4u;
            mbar_expect_tx(fullA[1], bytes);
            tma_bulk_1d(dstBase + TILE_F4 * 16u, X + (size_t)t1 * ROWS * DIMS,
                        bytes, fullA[1]);
        }
    }

    int ph_e[NSTG] = {0, 0, 1};   // producer empty-wait parities (slot2 fresh)
    int ph_f[NSTG] = {0, 0, 0};   // consumer full-wait parities

    u64 held = ~0ull;             // sorted-ascending invariant
    u32 mhi  = 0xFFFFFFFFu;
    float wsum = 0.0f;
    int s = 0;

    for (int t = t0; t < tiles; t += NBLK) {
        if (tid == 0 && t + 2 * NBLK < tiles) {
            int s2 = s + 2; if (s2 >= NSTG) s2 -= NSTG;
            mbar_wait(emptyA[s2], (u32)ph_e[s2]); ph_e[s2] ^= 1;
            const int tn = t + 2 * NBLK;
            const int rows = min(ROWS, N - tn * ROWS);
            const u32 bytes = (u32)rows * DIMS * 4u;
            mbar_expect_tx(fullA[s2], bytes);
            tma_bulk_1d(dstBase + (u32)s2 * TILE_F4 * 16u,
                        X + (size_t)tn * ROWS * DIMS, bytes, fullA[s2]);
        }
        mbar_wait(fullA[s], (u32)ph_f[s]); ph_f[s] ^= 1;

        // compute: one thread = one row, rotated column order (conflict-free)
        const int grow = t * ROWS + tid;
        const float4* rp = smem + s * TILE_F4 + tid * 16;
        const float4* qp = qsd + (tid & 15);
        float s0 = 0.f, s1 = 0.f, s2v = 0.f, s3 = 0.f;
        #pragma unroll
        for (int k = 0; k < 16; k++) {
            const float4 x = rp[(tid + k) & 15];
            const float4 qq = qp[k];
            float d;
            d = x.x - qq.x; s0  = fmaf(d, d, s0);
            d = x.y - qq.y; s1  = fmaf(d, d, s1);
            d = x.z - qq.z; s2v = fmaf(d, d, s2v);
            d = x.w - qq.w; s3  = fmaf(d, d, s3);
        }
        float dist = sqrtf((s0 + s1) + (s2v + s3));
        if (grow >= N) dist = CUDART_INF_F;   // partial tile: stale smem guarded
        wsum += __expf(-dist);
        const u32 db = __float_as_uint(dist);

        if (db < mhi && grow < N) {
            const int p = atomicAdd(&wcnt[warp], 1);
            wbuf[warp][p] = ((u64)db << 32) | (u32)grow;
        }
        __syncwarp();
        if (wcnt[warp] >= 32)                 // warp-uniform; rare
            flush_cands(wbuf[warp], &wcnt[warp], held, mhi, lane);

        mbar_arrive(emptyA[s]);               // issues after FMAs consumed LDS data
        s++; if (s == NSTG) s = 0;
    }
    if (wcnt[warp] > 0)
        flush_cands(wbuf[warp], &wcnt[warp], held, mhi, lane);

    // ---- per-block epilogue: sorted top-32 + partial Z ----
    s_lists[warp][lane] = held;
    #pragma unroll
    for (int off = 16; off; off >>= 1) wsum += __shfl_xor_sync(0xffffffffu, wsum, off);
    if (lane == 0) s_z[warp] = wsum;
    __syncthreads();

    if (warp == 0) {
        u64 a = s_lists[0][lane];
        #pragma unroll
        for (int w = 1; w < NWRP; w++) a = merge_sorted(a, s_lists[w][lane], lane);
        g_btop[blockIdx.x * KSEL + lane] = a;
        if (lane == 0) {
            float z = 0.0f;
            #pragma unroll
            for (int w = 0; w < NWRP; w++) z += s_z[w];
            g_bz[blockIdx.x] = z;
        }
    }

    // ---- tier-1 election: last block of each 37-block group ----
    const int gid = blockIdx.x / GSZ;
    const int b0  = gid * GSZ;
    __threadfence();
    __syncthreads();
    if (tid == 0) amLast1 = (atomicAdd(&g_c1[gid], 1) == GSZ - 1);
    __syncthreads();
    if (!amLast1) return;
    if (tid == 0) g_c1[gid] = 0;

    {   // merge this group's 37 sorted lists (4 warps, ~9 each, 1-compare skip)
        u64 h2 = g_btop[(b0 + warp) * KSEL + lane];
        u64 hmax = __shfl_sync(0xffffffffu, h2, 31);
        int b = b0 + warp + NWRP;
        u64 e = (b < b0 + GSZ) ? g_btop[b * KSEL + lane] : ~0ull;
        for (; b < b0 + GSZ; b += NWRP) {
            const int bn = b + NWRP;
            const u64 e_next = (bn < b0 + GSZ) ? g_btop[bn * KSEL + lane] : ~0ull;
            const u64 bmin = __shfl_sync(0xffffffffu, e, 0);
            if (bmin < hmax) {
                h2 = merge_sorted(h2, e, lane);
                hmax = __shfl_sync(0xffffffffu, h2, 31);
            }
            e = e_next;
        }
        s_lists[warp][lane] = h2;
        float z = 0.0f;
        for (int i = tid; i < GSZ; i += T1) z += g_bz[b0 + i];
        #pragma unroll
        for (int off = 16; off; off >>= 1) z += __shfl_xor_sync(0xffffffffu, z, off);
        if (lane == 0) s_z[warp] = z;
        __syncthreads();
        if (warp == 0) {
            u64 a = s_lists[0][lane];
            #pragma unroll
            for (int w = 1; w < NWRP; w++) a = merge_sorted(a, s_lists[w][lane], lane);
            g_gtop[gid * KSEL + lane] = a;
            if (lane == 0) {
                float zz = 0.0f;
                #pragma unroll
                for (int w = 0; w < NWRP; w++) zz += s_z[w];
                g_gz[gid] = zz;
            }
        }
    }

    // ---- tier-2 election: last of the 8 group-finishers ----
    __threadfence();
    __syncthreads();
    if (tid == 0) amLast2 = (atomicAdd(&g_c2, 1) == NGRP - 1);
    __syncthreads();
    if (!amLast2) return;
    if (tid == 0) g_c2 = 0;

    {   // merge 8 group lists (one per warp, then 4-way tree in warp 0)
        u64 h3 = g_gtop[warp * KSEL + lane];
        const int gi = warp + NWRP;
        if (gi < NGRP) h3 = merge_sorted(h3, g_gtop[gi * KSEL + lane], lane);
        s_lists[warp][lane] = h3;
        float z = 0.0f;
        for (int i = tid; i < NGRP; i += T1) z += g_gz[i];
        #pragma unroll
        for (int off = 16; off; off >>= 1) z += __shfl_xor_sync(0xffffffffu, z, off);
        if (lane == 0) s_z[warp] = z;
        __syncthreads();
        if (warp == 0) {
            u64 a = s_lists[0][lane];
            #pragma unroll
            for (int w = 1; w < NWRP; w++) a = merge_sorted(a, s_lists[w][lane], lane);
            if (a == ~0ull) { wv[lane] = 0.0f; iv[lane] = 0; }
            else {
                wv[lane] = __expf(-__uint_as_float((u32)(a >> 32)));
                iv[lane] = (int)(u32)a;
            }
            if (lane == 0) {
                float t2 = 0.0f;
                #pragma unroll
                for (int w = 0; w < NWRP; w++) t2 += s_z[w];
                zinv_s = 1.0f / t2;
            }
        }
        __syncthreads();
        if (tid < DIMS) {
            float acc = 0.0f;
            #pragma unroll
            for (int k = 0; k < KSEL; k++)
                acc += wv[k] * __ldg(Y + (size_t)iv[k] * DIMS + tid);
            out[tid] = acc * zinv_s;
        }
    }
}

extern "C" void kernel_launch(void* const* d_in, const int* in_sizes, int n_in,
                              void* d_out, int out_size) {
    const float* X = (const float*)d_in[0];
    const float* Y = (const float*)d_in[1];
    const float* q = (const float*)d_in[2];
    float* out = (float*)d_out;
    const int N = in_sizes[0] / DIMS;

    const int smemBytes = (NSTG * TILE_F4 + 32) * (int)sizeof(float4);  // ~98.8 KB
    cudaFuncSetAttribute(knn_fused, cudaFuncAttributeMaxDynamicSharedMemorySize,
                         smemBytes);
    knn_fused<<<NBLK, T1, smemBytes>>>(X, Y, q, out, N);
}